// round 16
// baseline (speedup 1.0000x reference)
#include <cuda_runtime.h>
#include <cstdint>
#include <cstddef>

#define D    4096
#define NH   32
#define H    128
#define S    4096
#define KMASK (-2.3819763e+38f)

// ---------------- scratch (device globals; no allocation allowed) ----------
__device__ __align__(16) float g_qkvp[16 * 96 * 128];   // qkv gemv partials
__device__ __align__(16) float g_q[NH * H];             // rope'd + scaled q
__device__ __align__(16) float g_knew[NH * H];          // rope'd new k row
__device__ __align__(16) float g_vnew[NH * H];          // new v row
__device__ float g_pm[NH * 64];                         // per-chunk max
__device__ float g_pl[NH * 64];                         // per-chunk sum
__device__ __align__(16) float g_pacc[NH * 64 * H];     // [n][c][h] p·v partials
__device__ __align__(16) float g_opart[128 * D];        // [nh-chunk][d]
__device__ int g_sncnt[96];                             // per-sn tickets

// ---------------- K1: qkv partial + fused rope/scatter ---------------------
// grid (96, 16): blockIdx.x = s*32+n, blockIdx.y = D-chunk of 256.
// Last block per sn (ticket) reduces the 16 partials and does RoPE+scatter.
__global__ void __launch_bounds__(128) k_qkv_fused(const float* __restrict__ x,
                                                   const float* __restrict__ w,
                                                   const int* __restrict__ segp,
                                                   const int* __restrict__ tsp,
                                                   float* __restrict__ k_out,
                                                   float* __restrict__ v_out) {
    int sn = blockIdx.x;
    int dchunk = blockIdx.y;
    int tid = threadIdx.x;
    int hv = tid & 31;
    int ds = tid >> 5;

    __shared__ float xs[256];
    int dbase = dchunk * 256;
    for (int i = tid; i < 256; i += 128) xs[i] = x[dbase + i];
    __syncthreads();

    const float4* wv = (const float4*)(w + (size_t)sn * D * H + (size_t)dbase * H);
    float4 acc = make_float4(0.f, 0.f, 0.f, 0.f);
    int d0 = ds * 64;
#pragma unroll 16
    for (int d = d0; d < d0 + 64; ++d) {
        float xv = xs[d];
        float4 wq = __ldcs(&wv[d * 32 + hv]);     // single-use stream
        acc.x += xv * wq.x; acc.y += xv * wq.y;
        acc.z += xv * wq.z; acc.w += xv * wq.w;
    }

    __shared__ float4 racc[4][32];
    racc[ds][hv] = acc;
    __syncthreads();
    if (tid < 32) {
        float4 t = racc[0][hv];
#pragma unroll
        for (int wdx = 1; wdx < 4; ++wdx) {
            float4 o = racc[wdx][hv];
            t.x += o.x; t.y += o.y; t.z += o.z; t.w += o.w;
        }
        ((float4*)g_qkvp)[((size_t)dchunk * 96 + sn) * 32 + hv] = t;
    }

    // ---- ticket: last block of this sn does the rope/scatter ----
    __threadfence();
    __shared__ bool last;
    if (tid == 0) last = (atomicAdd(&g_sncnt[sn], 1) == 15);
    __syncthreads();
    if (!last) return;
    if (tid == 0) g_sncnt[sn] = 0;                // reset for next graph replay

    int h = tid;
    int s = sn >> 5, n = sn & 31;
    float val = 0.f;
#pragma unroll
    for (int p = 0; p < 16; ++p) val += g_qkvp[((size_t)p * 96 + sn) * 128 + h];

    __shared__ float sm[128];
    sm[h] = val;
    __syncthreads();

    int ts = tsp[0];
    if (s == 2) {
        g_vnew[n * 128 + h] = val;
        v_out[((size_t)ts * NH + n) * H + h] = val;
        return;
    }
    float pos = (float)segp[0];
    int i = h & 63;
    float timescale = powf(10000.f, (float)i * (1.f / 64.f));
    float ang = pos / timescale;
    float sn_, cs;
    sincosf(ang, &sn_, &cs);
    float out;
    if (h < 64) out = sm[h] * cs - sm[h + 64] * sn_;
    else        out = sm[h] * cs + sm[h - 64] * sn_;
    if (s == 0) {
        g_q[n * 128 + h] = out * 0.08838834764831845f;  // head_dim^-0.5
    } else {
        g_knew[n * 128 + h] = out;
        k_out[((size_t)ts * NH + n) * H + h] = out;
    }
}

// ---------------- K3: flash attention + k/v cache copy ---------------------
// grid (64 s-chunks of 64, NH), block 256 = 8 warps; warp does 8 s-rows.
__global__ void __launch_bounds__(256) k_flash(const float* __restrict__ k_in,
                                               const float* __restrict__ v_in,
                                               const float* __restrict__ mask,
                                               const int* __restrict__ tsp,
                                               float* __restrict__ k_out,
                                               float* __restrict__ v_out) {
    int warp = threadIdx.x >> 5;
    int lane = threadIdx.x & 31;
    int n = blockIdx.y;
    int c = blockIdx.x;
    int s0 = c * 64 + warp * 8;
    int ts = tsp[0];

    float4 qq = ((const float4*)g_q)[n * 32 + lane];

    // ---- front-batched loads: K and V together (MLP 16) ----
    float4 kk[8], vv[8];
#pragma unroll
    for (int i = 0; i < 8; ++i) {
        int s = s0 + i;
        size_t ridx = (((size_t)s * NH + n) * H) >> 2;
        bool nw = (s != ts);
        kk[i] = nw ? __ldcs(&((const float4*)k_in)[ridx + lane])
                   : ((const float4*)g_knew)[n * 32 + lane];
        vv[i] = nw ? __ldcs(&((const float4*)v_in)[ridx + lane])
                   : ((const float4*)g_vnew)[n * 32 + lane];
    }
    // ---- cache copies (streaming stores) ----
#pragma unroll
    for (int i = 0; i < 8; ++i) {
        int s = s0 + i;
        if (s != ts) {
            size_t ridx = (((size_t)s * NH + n) * H) >> 2;
            __stcs(&((float4*)k_out)[ridx + lane], kk[i]);
            __stcs(&((float4*)v_out)[ridx + lane], vv[i]);
        }
    }

    float lg[8];
#pragma unroll
    for (int i = 0; i < 8; ++i) {
        int s = s0 + i;
        float dot = kk[i].x * qq.x + kk[i].y * qq.y + kk[i].z * qq.z + kk[i].w * qq.w;
#pragma unroll
        for (int off = 16; off; off >>= 1)
            dot += __shfl_xor_sync(0xffffffffu, dot, off);
        lg[i] = (mask[s] >= 0.5f * KMASK) ? dot : KMASK;
    }

    // warp-local softmax over 8 rows
    float m = lg[0];
#pragma unroll
    for (int i = 1; i < 8; ++i) m = fmaxf(m, lg[i]);
    float p[8], l = 0.f;
#pragma unroll
    for (int i = 0; i < 8; ++i) { p[i] = __expf(lg[i] - m); l += p[i]; }

    float4 acc = make_float4(0.f, 0.f, 0.f, 0.f);
#pragma unroll
    for (int i = 0; i < 8; ++i) {
        acc.x += p[i] * vv[i].x; acc.y += p[i] * vv[i].y;
        acc.z += p[i] * vv[i].z; acc.w += p[i] * vv[i].w;
    }

    // ---- block merge across 8 warps ----
    __shared__ float4 red[8][32];
    __shared__ float sm_m[8], sm_l[8];
    red[warp][lane] = acc;
    if (lane == 0) { sm_m[warp] = m; sm_l[warp] = l; }
    __syncthreads();
    if (warp == 0) {
        float bm = sm_m[0];
#pragma unroll
        for (int w = 1; w < 8; ++w) bm = fmaxf(bm, sm_m[w]);
        float bl = 0.f;
        float4 t = make_float4(0.f, 0.f, 0.f, 0.f);
#pragma unroll
        for (int w = 0; w < 8; ++w) {
            float e = __expf(sm_m[w] - bm);
            bl += sm_l[w] * e;
            float4 o = red[w][lane];
            t.x += e * o.x; t.y += e * o.y; t.z += e * o.z; t.w += e * o.w;
        }
        ((float4*)g_pacc)[((size_t)n * 64 + c) * 32 + lane] = t;   // [n][c][h]
        if (lane == 0) {
            g_pm[n * 64 + c] = bm;
            g_pl[n * 64 + c] = bl;
        }
    }
}

// ---------------- K4: output GEMV with fused combine -----------------------
// grid (4 d-tiles of 1024 floats, 128 nh-chunks of 32), block 256.
__global__ void __launch_bounds__(256) k_out_gemv(const float* __restrict__ w_out) {
    int tid = threadIdx.x;
    int nh0 = blockIdx.y * 32;
    int n  = nh0 >> 7;                           // head
    int hb = nh0 & 127;                          // 0/32/64/96 within head

    __shared__ float s_m[64], s_l[64], s_e[64];
    __shared__ float s_mg, s_linv;
    __shared__ float part[8][32];
    __shared__ float enc_s[32];

    if (tid < 64) {
        s_m[tid] = g_pm[n * 64 + tid];
        s_l[tid] = g_pl[n * 64 + tid];
    }
    __syncthreads();
    if (tid < 32) {
        float m = fmaxf(s_m[tid], s_m[tid + 32]);
#pragma unroll
        for (int off = 16; off; off >>= 1)
            m = fmaxf(m, __shfl_xor_sync(0xffffffffu, m, off));
        if (tid == 0) s_mg = m;
    }
    __syncthreads();
    if (tid < 64) s_e[tid] = __expf(s_m[tid] - s_mg);
    __syncthreads();
    if (tid < 32) {
        float l = s_l[tid] * s_e[tid] + s_l[tid + 32] * s_e[tid + 32];
#pragma unroll
        for (int off = 16; off; off >>= 1)
            l += __shfl_xor_sync(0xffffffffu, l, off);
        if (tid == 0) s_linv = 1.f / l;
    }
    __syncthreads();

    {
        int hl = tid & 31;                        // h within chunk
        int grp = tid >> 5;                       // 0..7, 8 chunks each
        const float* base = g_pacc + (size_t)n * 64 * 128 + hb + hl;
        float acc = 0.f;
        int c0 = grp * 8;
#pragma unroll
        for (int cc = c0; cc < c0 + 8; ++cc)
            acc += base[(size_t)cc * 128] * s_e[cc];
        part[grp][hl] = acc;
    }
    __syncthreads();
    if (tid < 32) {
        float v = 0.f;
#pragma unroll
        for (int g = 0; g < 8; ++g) v += part[g][tid];
        enc_s[tid] = v * s_linv;
    }
    __syncthreads();

    // ---- GEMV main loop: thread owns one float4 over d ----
    int d4 = blockIdx.x * 256 + tid;             // float4 index over d (0..1023)
    const float4* wv = (const float4*)w_out;
    float4 acc = make_float4(0.f, 0.f, 0.f, 0.f);
#pragma unroll 8
    for (int j = 0; j < 32; ++j) {
        float e = enc_s[j];
        float4 w4 = __ldcs(&wv[(size_t)(nh0 + j) * (D / 4) + d4]);  // single-use
        acc.x += e * w4.x; acc.y += e * w4.y;
        acc.z += e * w4.z; acc.w += e * w4.w;
    }
    ((float4*)g_opart)[(size_t)blockIdx.y * (D / 4) + d4] = acc;
}

// ---------------- K5: final output reduce ----------------------------------
// grid 8, block 512: 4 threads per d4, each sums 32 chunks, smem merge
__global__ void __launch_bounds__(512) k_out_reduce(float* __restrict__ attn) {
    int tid = threadIdx.x;
    int d4l = tid & 127;
    int grp = tid >> 7;                           // 0..3
    int d4 = blockIdx.x * 128 + d4l;

    float4 v = make_float4(0.f, 0.f, 0.f, 0.f);
    int c0 = grp * 32;
#pragma unroll 8
    for (int c = c0; c < c0 + 32; ++c) {
        float4 o = ((const float4*)g_opart)[(size_t)c * (D / 4) + d4];
        v.x += o.x; v.y += o.y; v.z += o.z; v.w += o.w;
    }

    __shared__ float4 sred[4][128];
    sred[grp][d4l] = v;
    __syncthreads();
    if (tid < 128) {
        float4 a = sred[0][d4l], b = sred[1][d4l];
        float4 c = sred[2][d4l], d = sred[3][d4l];
        float4 r;
        r.x = (a.x + b.x) + (c.x + d.x);
        r.y = (a.y + b.y) + (c.y + d.y);
        r.z = (a.z + b.z) + (c.z + d.z);
        r.w = (a.w + b.w) + (c.w + d.w);
        ((float4*)attn)[d4] = r;
    }
}

// ---------------- launch ----------------------------------------------------
extern "C" void kernel_launch(void* const* d_in, const int* in_sizes, int n_in,
                              void* d_out, int out_size) {
    const float* x      = (const float*)d_in[0];
    const float* w_qkv  = (const float*)d_in[1];
    const float* w_out  = (const float*)d_in[2];
    const float* k_in   = (const float*)d_in[3];
    const float* v_in   = (const float*)d_in[4];
    const float* mask   = (const float*)d_in[5];
    const int*   segp   = (const int*)d_in[6];
    const int*   tsp    = (const int*)d_in[7];

    float* out   = (float*)d_out;
    float* k_out = out;
    float* v_out = out + (size_t)S * NH * H;
    float* attn  = out + 2ull * S * NH * H;

    k_qkv_fused<<<dim3(96, 16), 128>>>(x, w_qkv, segp, tsp, k_out, v_out);
    k_flash<<<dim3(64, NH), 256>>>(k_in, v_in, mask, tsp, k_out, v_out);
    k_out_gemv<<<dim3(4, 128), 256>>>(w_out);
    k_out_reduce<<<8, 512>>>(attn);
}

// round 17
// speedup vs baseline: 1.0134x; 1.0134x over previous
#include <cuda_runtime.h>
#include <cstdint>
#include <cstddef>

#define D    4096
#define NH   32
#define H    128
#define S    4096
#define KMASK (-2.3819763e+38f)

// ---------------- scratch (device globals; no allocation allowed) ----------
__device__ __align__(16) float g_qkvp[16 * 96 * 128];   // qkv gemv partials
__device__ __align__(16) float g_q[NH * H];             // rope'd + scaled q
__device__ __align__(16) float g_knew[NH * H];          // rope'd new k row
__device__ __align__(16) float g_vnew[NH * H];          // new v row
__device__ float g_pm[NH * 64];                         // per-chunk max
__device__ float g_pl[NH * 64];                         // per-chunk sum
__device__ __align__(16) float g_pacc[NH * 64 * H];     // [n][c][h] p·v partials
__device__ __align__(16) float g_opart[128 * D];        // [nh-chunk][d]
__device__ int g_sncnt[96];                             // per-sn tickets

// ---------------- K1: qkv partial + fused rope/scatter ---------------------
// grid (96, 16): blockIdx.x = s*32+n, blockIdx.y = D-chunk of 256.
// Last block per sn (ticket) reduces the 16 partials and does RoPE+scatter.
__global__ void __launch_bounds__(128) k_qkv_fused(const float* __restrict__ x,
                                                   const float* __restrict__ w,
                                                   const int* __restrict__ segp,
                                                   const int* __restrict__ tsp,
                                                   float* __restrict__ k_out,
                                                   float* __restrict__ v_out) {
    int sn = blockIdx.x;
    int dchunk = blockIdx.y;
    int tid = threadIdx.x;
    int hv = tid & 31;
    int ds = tid >> 5;

    __shared__ float xs[256];
    int dbase = dchunk * 256;
    for (int i = tid; i < 256; i += 128) xs[i] = x[dbase + i];
    __syncthreads();

    const float4* wv = (const float4*)(w + (size_t)sn * D * H + (size_t)dbase * H);
    float4 acc = make_float4(0.f, 0.f, 0.f, 0.f);
    int d0 = ds * 64;
#pragma unroll 16
    for (int d = d0; d < d0 + 64; ++d) {
        float xv = xs[d];
        float4 wq = __ldcs(&wv[d * 32 + hv]);     // single-use stream
        acc.x += xv * wq.x; acc.y += xv * wq.y;
        acc.z += xv * wq.z; acc.w += xv * wq.w;
    }

    __shared__ float4 racc[4][32];
    racc[ds][hv] = acc;
    __syncthreads();
    if (tid < 32) {
        float4 t = racc[0][hv];
#pragma unroll
        for (int wdx = 1; wdx < 4; ++wdx) {
            float4 o = racc[wdx][hv];
            t.x += o.x; t.y += o.y; t.z += o.z; t.w += o.w;
        }
        ((float4*)g_qkvp)[((size_t)dchunk * 96 + sn) * 32 + hv] = t;
    }

    // ---- ticket: last block of this sn does the rope/scatter ----
    __threadfence();
    __shared__ bool last;
    if (tid == 0) last = (atomicAdd(&g_sncnt[sn], 1) == 15);
    __syncthreads();
    if (!last) return;
    if (tid == 0) g_sncnt[sn] = 0;                // reset for next graph replay

    int h = tid;
    int s = sn >> 5, n = sn & 31;
    float val = 0.f;
#pragma unroll
    for (int p = 0; p < 16; ++p) val += g_qkvp[((size_t)p * 96 + sn) * 128 + h];

    __shared__ float sm[128];
    sm[h] = val;
    __syncthreads();

    int ts = tsp[0];
    if (s == 2) {
        g_vnew[n * 128 + h] = val;
        v_out[((size_t)ts * NH + n) * H + h] = val;
        return;
    }
    float pos = (float)segp[0];
    int i = h & 63;
    float timescale = powf(10000.f, (float)i * (1.f / 64.f));
    float ang = pos / timescale;
    float sn_, cs;
    sincosf(ang, &sn_, &cs);
    float out;
    if (h < 64) out = sm[h] * cs - sm[h + 64] * sn_;
    else        out = sm[h] * cs + sm[h - 64] * sn_;
    if (s == 0) {
        g_q[n * 128 + h] = out * 0.08838834764831845f;  // head_dim^-0.5
    } else {
        g_knew[n * 128 + h] = out;
        k_out[((size_t)ts * NH + n) * H + h] = out;
    }
}

// ---------------- K3: flash attention + k/v cache copy ---------------------
// grid (64 s-chunks of 64, NH), block 256 = 8 warps; warp does 8 s-rows.
__global__ void __launch_bounds__(256) k_flash(const float* __restrict__ k_in,
                                               const float* __restrict__ v_in,
                                               const float* __restrict__ mask,
                                               const int* __restrict__ tsp,
                                               float* __restrict__ k_out,
                                               float* __restrict__ v_out) {
    int warp = threadIdx.x >> 5;
    int lane = threadIdx.x & 31;
    int n = blockIdx.y;
    int c = blockIdx.x;
    int s0 = c * 64 + warp * 8;
    int ts = tsp[0];

    float4 qq = ((const float4*)g_q)[n * 32 + lane];

    // ---- front-batched loads: K and V together (MLP 16) ----
    float4 kk[8], vv[8];
#pragma unroll
    for (int i = 0; i < 8; ++i) {
        int s = s0 + i;
        size_t ridx = (((size_t)s * NH + n) * H) >> 2;
        bool nw = (s != ts);
        kk[i] = nw ? __ldcs(&((const float4*)k_in)[ridx + lane])
                   : ((const float4*)g_knew)[n * 32 + lane];
        vv[i] = nw ? __ldcs(&((const float4*)v_in)[ridx + lane])
                   : ((const float4*)g_vnew)[n * 32 + lane];
    }
    // ---- cache copies (streaming stores) ----
#pragma unroll
    for (int i = 0; i < 8; ++i) {
        int s = s0 + i;
        if (s != ts) {
            size_t ridx = (((size_t)s * NH + n) * H) >> 2;
            __stcs(&((float4*)k_out)[ridx + lane], kk[i]);
            __stcs(&((float4*)v_out)[ridx + lane], vv[i]);
        }
    }

    float lg[8];
#pragma unroll
    for (int i = 0; i < 8; ++i) {
        int s = s0 + i;
        float dot = kk[i].x * qq.x + kk[i].y * qq.y + kk[i].z * qq.z + kk[i].w * qq.w;
#pragma unroll
        for (int off = 16; off; off >>= 1)
            dot += __shfl_xor_sync(0xffffffffu, dot, off);
        lg[i] = (mask[s] >= 0.5f * KMASK) ? dot : KMASK;
    }

    // warp-local softmax over 8 rows
    float m = lg[0];
#pragma unroll
    for (int i = 1; i < 8; ++i) m = fmaxf(m, lg[i]);
    float p[8], l = 0.f;
#pragma unroll
    for (int i = 0; i < 8; ++i) { p[i] = __expf(lg[i] - m); l += p[i]; }

    float4 acc = make_float4(0.f, 0.f, 0.f, 0.f);
#pragma unroll
    for (int i = 0; i < 8; ++i) {
        acc.x += p[i] * vv[i].x; acc.y += p[i] * vv[i].y;
        acc.z += p[i] * vv[i].z; acc.w += p[i] * vv[i].w;
    }

    // ---- block merge across 8 warps ----
    __shared__ float4 red[8][32];
    __shared__ float sm_m[8], sm_l[8];
    red[warp][lane] = acc;
    if (lane == 0) { sm_m[warp] = m; sm_l[warp] = l; }
    __syncthreads();
    if (warp == 0) {
        float bm = sm_m[0];
#pragma unroll
        for (int w = 1; w < 8; ++w) bm = fmaxf(bm, sm_m[w]);
        float bl = 0.f;
        float4 t = make_float4(0.f, 0.f, 0.f, 0.f);
#pragma unroll
        for (int w = 0; w < 8; ++w) {
            float e = __expf(sm_m[w] - bm);
            bl += sm_l[w] * e;
            float4 o = red[w][lane];
            t.x += e * o.x; t.y += e * o.y; t.z += e * o.z; t.w += e * o.w;
        }
        ((float4*)g_pacc)[((size_t)n * 64 + c) * 32 + lane] = t;   // [n][c][h]
        if (lane == 0) {
            g_pm[n * 64 + c] = bm;
            g_pl[n * 64 + c] = bl;
        }
    }
}

// ---------------- K4: output GEMV with fused combine -----------------------
// grid (4 d-tiles of 1024 floats, 128 nh-chunks of 32), block 256.
__global__ void __launch_bounds__(256) k_out_gemv(const float* __restrict__ w_out) {
    int tid = threadIdx.x;
    int nh0 = blockIdx.y * 32;
    int n  = nh0 >> 7;                           // head
    int hb = nh0 & 127;                          // 0/32/64/96 within head

    __shared__ float s_m[64], s_l[64], s_e[64];
    __shared__ float s_mg, s_linv;
    __shared__ float part[8][32];
    __shared__ float enc_s[32];

    if (tid < 64) {
        s_m[tid] = g_pm[n * 64 + tid];
        s_l[tid] = g_pl[n * 64 + tid];
    }
    __syncthreads();
    if (tid < 32) {
        float m = fmaxf(s_m[tid], s_m[tid + 32]);
#pragma unroll
        for (int off = 16; off; off >>= 1)
            m = fmaxf(m, __shfl_xor_sync(0xffffffffu, m, off));
        if (tid == 0) s_mg = m;
    }
    __syncthreads();
    if (tid < 64) s_e[tid] = __expf(s_m[tid] - s_mg);
    __syncthreads();
    if (tid < 32) {
        float l = s_l[tid] * s_e[tid] + s_l[tid + 32] * s_e[tid + 32];
#pragma unroll
        for (int off = 16; off; off >>= 1)
            l += __shfl_xor_sync(0xffffffffu, l, off);
        if (tid == 0) s_linv = 1.f / l;
    }
    __syncthreads();

    {
        int hl = tid & 31;                        // h within chunk
        int grp = tid >> 5;                       // 0..7, 8 chunks each
        const float* base = g_pacc + (size_t)n * 64 * 128 + hb + hl;
        float acc = 0.f;
        int c0 = grp * 8;
#pragma unroll
        for (int cc = c0; cc < c0 + 8; ++cc)
            acc += base[(size_t)cc * 128] * s_e[cc];
        part[grp][hl] = acc;
    }
    __syncthreads();
    if (tid < 32) {
        float v = 0.f;
#pragma unroll
        for (int g = 0; g < 8; ++g) v += part[g][tid];
        enc_s[tid] = v * s_linv;
    }
    __syncthreads();

    // ---- GEMV main loop: thread owns one float4 over d ----
    int d4 = blockIdx.x * 256 + tid;             // float4 index over d (0..1023)
    const float4* wv = (const float4*)w_out;
    float4 acc = make_float4(0.f, 0.f, 0.f, 0.f);
#pragma unroll 8
    for (int j = 0; j < 32; ++j) {
        float e = enc_s[j];
        float4 w4 = __ldcs(&wv[(size_t)(nh0 + j) * (D / 4) + d4]);  // single-use
        acc.x += e * w4.x; acc.y += e * w4.y;
        acc.z += e * w4.z; acc.w += e * w4.w;
    }
    ((float4*)g_opart)[(size_t)blockIdx.y * (D / 4) + d4] = acc;
}

// ---------------- K5: final output reduce (parallel, coalesced) ------------
// grid 32, block 256 = 8 warps. Warp owns 32 consecutive d4 for one
// 16-chunk group (coalesced 512B loads, 16 front-batched per thread);
// smem merge of the 8 groups.
__global__ void __launch_bounds__(256) k_out_reduce(float* __restrict__ attn) {
    int tid = threadIdx.x;
    int lane = tid & 31;
    int grp = tid >> 5;                           // 0..7
    int d4 = blockIdx.x * 32 + lane;

    float4 v = make_float4(0.f, 0.f, 0.f, 0.f);
    int c0 = grp * 16;
#pragma unroll
    for (int c = c0; c < c0 + 16; ++c) {
        float4 o = ((const float4*)g_opart)[(size_t)c * (D / 4) + d4];
        v.x += o.x; v.y += o.y; v.z += o.z; v.w += o.w;
    }

    __shared__ float4 sred[8][32];
    sred[grp][lane] = v;
    __syncthreads();
    if (tid < 32) {
        float4 r = sred[0][lane];
#pragma unroll
        for (int g = 1; g < 8; ++g) {
            float4 o = sred[g][lane];
            r.x += o.x; r.y += o.y; r.z += o.z; r.w += o.w;
        }
        ((float4*)attn)[d4] = r;
    }
}

// ---------------- launch ----------------------------------------------------
extern "C" void kernel_launch(void* const* d_in, const int* in_sizes, int n_in,
                              void* d_out, int out_size) {
    const float* x      = (const float*)d_in[0];
    const float* w_qkv  = (const float*)d_in[1];
    const float* w_out  = (const float*)d_in[2];
    const float* k_in   = (const float*)d_in[3];
    const float* v_in   = (const float*)d_in[4];
    const float* mask   = (const float*)d_in[5];
    const int*   segp   = (const int*)d_in[6];
    const int*   tsp    = (const int*)d_in[7];

    float* out   = (float*)d_out;
    float* k_out = out;
    float* v_out = out + (size_t)S * NH * H;
    float* attn  = out + 2ull * S * NH * H;

    k_qkv_fused<<<dim3(96, 16), 128>>>(x, w_qkv, segp, tsp, k_out, v_out);
    k_flash<<<dim3(64, NH), 256>>>(k_in, v_in, mask, tsp, k_out, v_out);
    k_out_gemv<<<dim3(4, 128), 256>>>(w_out);
    k_out_reduce<<<32, 256>>>(attn);
}